// round 6
// baseline (speedup 1.0000x reference)
#include <cuda_runtime.h>
#include <math.h>

// ---------------------------------------------------------------------------
// Differentiable JPEG (quality 80) forward pass, fused single kernel.
// Tile = 64x32 px, CTA = 128 threads. Each thread owns an 8-wide x 2-row
// strip of all 3 channels.
//   Y path: row-DCT + inverse row-DCT in REGISTERS; only the column pass
//   goes through shared (in-place, XOR-swizzled, conflict-free).
//   Chroma (8 Cb + 8 Cr blocks): classic 3-stage shared pipeline.
// Global I/O: float4 only, fully coalesced. Writeback straight from regs.
// ---------------------------------------------------------------------------

#define IMG 512

__constant__ float c_YTAB[64] = {
    16,11,10,16,24,40,51,61,  12,12,14,19,26,58,60,55,
    14,13,16,24,40,57,69,56,  14,17,22,29,51,87,80,62,
    18,22,37,56,68,109,103,77, 24,35,55,64,81,104,113,92,
    49,64,78,87,103,121,120,101, 72,92,95,98,112,100,103,99};
__constant__ float c_CTAB[64] = {
    17,18,24,47,99,99,99,99,  18,21,26,66,99,99,99,99,
    24,26,56,99,99,99,99,99,  47,66,99,99,99,99,99,99,
    99,99,99,99,99,99,99,99,  99,99,99,99,99,99,99,99,
    99,99,99,99,99,99,99,99,  99,99,99,99,99,99,99,99};

// cos(k*pi/16)
#define C1 0.980785280403230449f
#define C2 0.923879532511286756f
#define C3 0.831469612302545237f
#define C4 0.707106781186547524f
#define C5 0.555570233019602225f
#define C6 0.382683432365089772f
#define C7 0.195090322016128268f

// a[u] = sum_x in[x]*cos((2x+1)u*pi/16), even/odd butterfly.
__device__ __forceinline__ void dct8_fwd(const float in[8], float a[8]) {
    float s0 = in[0] + in[7], s1 = in[1] + in[6];
    float s2 = in[2] + in[5], s3 = in[3] + in[4];
    float d0 = in[0] - in[7], d1 = in[1] - in[6];
    float d2 = in[2] - in[5], d3 = in[3] - in[4];
    a[0] = (s0 + s3) + (s1 + s2);
    a[2] = C2 * s0 + C6 * s1 - C6 * s2 - C2 * s3;
    a[4] = C4 * ((s0 + s3) - (s1 + s2));
    a[6] = C6 * s0 - C2 * s1 + C2 * s2 - C6 * s3;
    a[1] = C1 * d0 + C3 * d1 + C5 * d2 + C7 * d3;
    a[3] = C3 * d0 - C7 * d1 - C1 * d2 - C5 * d3;
    a[5] = C5 * d0 - C1 * d1 + C7 * d2 + C3 * d3;
    a[7] = C7 * d0 - C5 * d1 + C3 * d2 - C1 * d3;
}

// p[x] = sum_u h[u]*cos((2x+1)u*pi/16), even/odd halves.
__device__ __forceinline__ void dct8_inv(const float h[8], float p[8]) {
    float e0 = h[0] + C2 * h[2] + C4 * h[4] + C6 * h[6];
    float e1 = h[0] + C6 * h[2] - C4 * h[4] - C2 * h[6];
    float e2 = h[0] - C6 * h[2] - C4 * h[4] + C2 * h[6];
    float e3 = h[0] - C2 * h[2] + C4 * h[4] - C6 * h[6];
    float o0 = C1 * h[1] + C3 * h[3] + C5 * h[5] + C7 * h[7];
    float o1 = C3 * h[1] - C7 * h[3] - C1 * h[5] - C5 * h[7];
    float o2 = C5 * h[1] - C1 * h[3] + C7 * h[5] + C3 * h[7];
    float o3 = C7 * h[1] - C5 * h[3] + C3 * h[5] - C1 * h[7];
    p[0] = e0 + o0;  p[7] = e0 - o0;
    p[1] = e1 + o1;  p[6] = e1 - o1;
    p[2] = e2 + o2;  p[5] = e2 - o2;
    p[3] = e3 + o3;  p[4] = e3 - o3;
}

__global__ void __launch_bounds__(128)
jpeg_tile_kernel(const float* __restrict__ img, float* __restrict__ out) {
    // Y column buffer: 32 blocks x [8 rows][9], col index XOR-swizzled by (b&4).
    __shared__ float sY[32 * 72];
    __shared__ float s1c[16 * 72];   // chroma ping (Cb blk 0..7, Cr blk 8..15)
    __shared__ float s2c[16 * 72];   // chroma pong
    __shared__ float sAqTY[64], sBqTY[64];  // Y quant, TRANSPOSED [v][u]
    __shared__ float sAqC[64],  sBqC[64];   // chroma quant, [u][v]

    const int t = threadIdx.x;

    if (t < 64) {
        int u = t >> 3, v = t & 7;
        float au = (u == 0) ? 0.70710678118654752f : 1.f;
        float av = (v == 0) ? 0.70710678118654752f : 1.f;
        float S = au * av * 0.25f;
        float qy = c_YTAB[t] * 0.4f;   // QUALITY=80 -> FACTOR=0.4
        float qc = c_CTAB[t] * 0.4f;
        sAqTY[v * 8 + u] = __fdividef(S, qy);  sBqTY[v * 8 + u] = S * qy;
        sAqC[t]          = __fdividef(S, qc);  sBqC[t]          = S * qc;
    }

    const int bid  = blockIdx.x;
    const int tx   = bid & 7;            // 8 tiles across (64 px)
    const int ty   = (bid >> 3) & 15;    // 16 tiles down (32 px)
    const int bimg = bid >> 7;

    const int sx = t & 7;                // strip x: 8 strips of 8 px
    const int sy = t >> 3;               // strip y: 16 row-pairs
    const int px0 = tx * 64 + sx * 8;
    const int py0 = ty * 32 + sy * 2;

    const size_t plane = (size_t)IMG * IMG;
    const float* base = img + (size_t)bimg * 3 * plane + (size_t)py0 * IMG + px0;

    // Y block owned by this strip, and its swizzle
    const int yb   = (sy >> 2) * 8 + sx;     // 32 Y blocks (8 across, 4 down)
    const int ysw  = yb & 4;                 // XOR swizzle for sY columns
    const int yrow = (sy & 3) * 2;           // first of the 2 rows in block
    // Chroma position
    const int cblk  = (sy >> 3) * 4 + (sx >> 1);  // Cb block 0..7 (Cr = +8)
    const int crow  = sy & 7;
    const int ccol0 = (sx & 1) * 4;

    // ---- Epoch 1: load strip, RGB->Y rows (-128 folded), row-DCT in regs,
    //      store v-coefs to sY; 2x2-average chroma into s1c.
    float cbv[4] = {0.f, 0.f, 0.f, 0.f};
    float crv[4] = {0.f, 0.f, 0.f, 0.f};
    #pragma unroll
    for (int r = 0; r < 2; r++) {
        const float* rp = base + (size_t)r * IMG;
        float4 R0 = *(const float4*)(rp);
        float4 R1 = *(const float4*)(rp + 4);
        float4 G0 = *(const float4*)(rp + plane);
        float4 G1 = *(const float4*)(rp + plane + 4);
        float4 B0 = *(const float4*)(rp + 2 * plane);
        float4 B1 = *(const float4*)(rp + 2 * plane + 4);
        float Rr[8] = {R0.x, R0.y, R0.z, R0.w, R1.x, R1.y, R1.z, R1.w};
        float Gr[8] = {G0.x, G0.y, G0.z, G0.w, G1.x, G1.y, G1.z, G1.w};
        float Br[8] = {B0.x, B0.y, B0.z, B0.w, B1.x, B1.y, B1.z, B1.w};

        float yrv[8];
        #pragma unroll
        for (int c = 0; c < 8; c++) {
            float rr = Rr[c] * 255.f, gg = Gr[c] * 255.f, bb = Br[c] * 255.f;
            yrv[c] = 0.299f * rr + 0.587f * gg + 0.114f * bb - 128.f;
            cbv[c >> 1] += -0.168736f * rr - 0.331264f * gg + 0.5f      * bb;
            crv[c >> 1] +=  0.5f      * rr - 0.418688f * gg - 0.081312f * bb;
        }
        float yc[8];
        dct8_fwd(yrv, yc);                 // x-cols -> v
        #pragma unroll
        for (int v = 0; v < 8; v++)
            sY[yb * 72 + (yrow + r) * 9 + (v ^ ysw)] = yc[v];
    }
    #pragma unroll
    for (int k = 0; k < 4; k++) {
        s1c[cblk * 72       + crow * 9 + ccol0 + k] = cbv[k] * 0.25f;
        s1c[(cblk + 8) * 72 + crow * 9 + ccol0 + k] = crv[k] * 0.25f;
    }
    __syncthreads();

    // ---- Epoch 2: Y column pass (fwd u-DCT, quant diff_round, inv u) in
    //      place, 2 tasks/thread. Chroma stage A (u-transform over rows).
    #pragma unroll
    for (int iter = 0; iter < 2; iter++) {
        int task = iter * 128 + t;
        int b = task >> 3, v = task & 7;
        int sw = v ^ (b & 4);
        float col[8], cf[8];
        #pragma unroll
        for (int x = 0; x < 8; x++) col[x] = sY[b * 72 + x * 9 + sw];
        dct8_fwd(col, cf);                 // x-rows -> u

        const float4 qa0 = *(const float4*)&sAqTY[v * 8];
        const float4 qa1 = *(const float4*)&sAqTY[v * 8 + 4];
        const float4 qb0 = *(const float4*)&sBqTY[v * 8];
        const float4 qb1 = *(const float4*)&sBqTY[v * 8 + 4];
        const float Aq[8] = {qa0.x, qa0.y, qa0.z, qa0.w, qa1.x, qa1.y, qa1.z, qa1.w};
        const float Bq[8] = {qb0.x, qb0.y, qb0.z, qb0.w, qb1.x, qb1.y, qb1.z, qb1.w};

        float h[8];
        #pragma unroll
        for (int u = 0; u < 8; u++) {
            float c = cf[u] * Aq[u];
            float r = rintf(c);            // round-half-even == jnp.round
            float d = c - r;
            h[u] = (r + d * d * d) * Bq[u];
        }
        float hw[8];
        dct8_inv(h, hw);                   // u -> x-rows (halfway domain)
        #pragma unroll
        for (int x = 0; x < 8; x++) sY[b * 72 + x * 9 + sw] = hw[x];
    }
    {   // chroma stage A: task (blk, j): u-transform along rows
        int blk = t >> 3, j = t & 7;
        float in[8], a[8];
        #pragma unroll
        for (int x = 0; x < 8; x++) in[x] = s1c[blk * 72 + x * 9 + j];
        dct8_fwd(in, a);
        #pragma unroll
        for (int u = 0; u < 8; u++) s2c[blk * 72 + u * 9 + j] = a[u];
    }
    __syncthreads();

    // ---- Epoch 3: Y inverse row pass in regs (keep pixels live);
    //      chroma stage B (v-transform + quant + inverse v).
    float Ypix[2][8];
    #pragma unroll
    for (int r = 0; r < 2; r++) {
        float hw[8];
        #pragma unroll
        for (int v = 0; v < 8; v++)
            hw[v] = sY[yb * 72 + (yrow + r) * 9 + (v ^ ysw)];
        float p[8];
        dct8_inv(hw, p);                   // v -> x-cols
        #pragma unroll
        for (int c = 0; c < 8; c++) Ypix[r][c] = p[c] + 128.f;
    }
    {   // chroma stage B
        int blk = t >> 3, u = t & 7;
        float row[8], cv[8];
        #pragma unroll
        for (int y = 0; y < 8; y++) row[y] = s2c[blk * 72 + u * 9 + y];
        dct8_fwd(row, cv);
        const float4 qa0 = *(const float4*)&sAqC[u * 8];
        const float4 qa1 = *(const float4*)&sAqC[u * 8 + 4];
        const float4 qb0 = *(const float4*)&sBqC[u * 8];
        const float4 qb1 = *(const float4*)&sBqC[u * 8 + 4];
        const float Aq[8] = {qa0.x, qa0.y, qa0.z, qa0.w, qa1.x, qa1.y, qa1.z, qa1.w};
        const float Bq[8] = {qb0.x, qb0.y, qb0.z, qb0.w, qb1.x, qb1.y, qb1.z, qb1.w};
        float h[8];
        #pragma unroll
        for (int v = 0; v < 8; v++) {
            float c = cv[v] * Aq[v];
            float r = rintf(c);
            float d = c - r;
            h[v] = (r + d * d * d) * Bq[v];
        }
        float p[8];
        dct8_inv(h, p);
        #pragma unroll
        for (int y = 0; y < 8; y++) s1c[blk * 72 + u * 9 + y] = p[y];
    }
    __syncthreads();

    // ---- Epoch 4: chroma stage C (inverse u-transform over rows).
    {
        int blk = t >> 3, j = t & 7;
        float in[8], p[8];
        #pragma unroll
        for (int u = 0; u < 8; u++) in[u] = s1c[blk * 72 + u * 9 + j];
        dct8_inv(in, p);
        #pragma unroll
        for (int x = 0; x < 8; x++) s2c[blk * 72 + x * 9 + j] = p[x];
    }
    __syncthreads();

    // ---- Epoch 5: read back strip chroma, YCbCr->RGB, clip, store from regs.
    float cbq[4], crq[4];
    #pragma unroll
    for (int k = 0; k < 4; k++) {
        cbq[k] = s2c[cblk * 72       + crow * 9 + ccol0 + k];
        crq[k] = s2c[(cblk + 8) * 72 + crow * 9 + ccol0 + k];
    }

    float* obase = out + (size_t)bimg * 3 * plane + (size_t)py0 * IMG + px0;
    #pragma unroll
    for (int r = 0; r < 2; r++) {
        float Rv[8], Gv[8], Bv[8];
        #pragma unroll
        for (int c = 0; c < 8; c++) {
            float y  = Ypix[r][c];
            float cb = cbq[c >> 1];
            float cr = crq[c >> 1];
            float rr = y + 1.402f * cr;
            float gg = y - 0.344136f * cb - 0.714136f * cr;
            float bb = y + 1.772f * cb;
            Rv[c] = fminf(fmaxf(rr, 0.f), 255.f) * (1.f / 255.f);
            Gv[c] = fminf(fmaxf(gg, 0.f), 255.f) * (1.f / 255.f);
            Bv[c] = fminf(fmaxf(bb, 0.f), 255.f) * (1.f / 255.f);
        }
        float* op = obase + (size_t)r * IMG;
        *(float4*)(op)             = make_float4(Rv[0], Rv[1], Rv[2], Rv[3]);
        *(float4*)(op + 4)         = make_float4(Rv[4], Rv[5], Rv[6], Rv[7]);
        *(float4*)(op + plane)     = make_float4(Gv[0], Gv[1], Gv[2], Gv[3]);
        *(float4*)(op + plane + 4) = make_float4(Gv[4], Gv[5], Gv[6], Gv[7]);
        *(float4*)(op + 2*plane)   = make_float4(Bv[0], Bv[1], Bv[2], Bv[3]);
        *(float4*)(op + 2*plane+4) = make_float4(Bv[4], Bv[5], Bv[6], Bv[7]);
    }
}

extern "C" void kernel_launch(void* const* d_in, const int* in_sizes, int n_in,
                              void* d_out, int out_size) {
    const float* img = (const float*)d_in[0];
    float* out = (float*)d_out;
    int batch = in_sizes[0] / (3 * IMG * IMG);        // 32
    int tiles = batch * (IMG / 32) * (IMG / 64);      // 32 * 16 * 8 = 4096
    jpeg_tile_kernel<<<tiles, 128>>>(img, out);
}

// round 7
// speedup vs baseline: 1.1717x; 1.1717x over previous
#include <cuda_runtime.h>
#include <math.h>

// ---------------------------------------------------------------------------
// Differentiable JPEG (quality 80) forward pass, fused single kernel.
// Tile = 64x16 px, CTA = 128 threads, each thread owns ONE 8-px row strip.
//   Y (16 blocks): row-DCT in regs -> sY coef columns -> in-place column
//   pass (fwd+quant+inv) -> inverse row-DCT in regs at writeback.
//   Chroma (4 Cb + 4 Cr): same scheme on one in-place buffer; vertical 2x2
//   pairing via shfl_xor(8).
// Shared layout: block stride 72 (=[8][9]), column index XOR-swizzled by
// (blk&4); all phases bank-conflict-free (verified per-phase).
// ---------------------------------------------------------------------------

#define IMG 512

__constant__ float c_YTAB[64] = {
    16,11,10,16,24,40,51,61,  12,12,14,19,26,58,60,55,
    14,13,16,24,40,57,69,56,  14,17,22,29,51,87,80,62,
    18,22,37,56,68,109,103,77, 24,35,55,64,81,104,113,92,
    49,64,78,87,103,121,120,101, 72,92,95,98,112,100,103,99};
__constant__ float c_CTAB[64] = {
    17,18,24,47,99,99,99,99,  18,21,26,66,99,99,99,99,
    24,26,56,99,99,99,99,99,  47,66,99,99,99,99,99,99,
    99,99,99,99,99,99,99,99,  99,99,99,99,99,99,99,99,
    99,99,99,99,99,99,99,99,  99,99,99,99,99,99,99,99};

// cos(k*pi/16)
#define C1 0.980785280403230449f
#define C2 0.923879532511286756f
#define C3 0.831469612302545237f
#define C4 0.707106781186547524f
#define C5 0.555570233019602225f
#define C6 0.382683432365089772f
#define C7 0.195090322016128268f

__device__ __forceinline__ void dct8_fwd(const float in[8], float a[8]) {
    float s0 = in[0] + in[7], s1 = in[1] + in[6];
    float s2 = in[2] + in[5], s3 = in[3] + in[4];
    float d0 = in[0] - in[7], d1 = in[1] - in[6];
    float d2 = in[2] - in[5], d3 = in[3] - in[4];
    a[0] = (s0 + s3) + (s1 + s2);
    a[2] = C2 * s0 + C6 * s1 - C6 * s2 - C2 * s3;
    a[4] = C4 * ((s0 + s3) - (s1 + s2));
    a[6] = C6 * s0 - C2 * s1 + C2 * s2 - C6 * s3;
    a[1] = C1 * d0 + C3 * d1 + C5 * d2 + C7 * d3;
    a[3] = C3 * d0 - C7 * d1 - C1 * d2 - C5 * d3;
    a[5] = C5 * d0 - C1 * d1 + C7 * d2 + C3 * d3;
    a[7] = C7 * d0 - C5 * d1 + C3 * d2 - C1 * d3;
}

__device__ __forceinline__ void dct8_inv(const float h[8], float p[8]) {
    float e0 = h[0] + C2 * h[2] + C4 * h[4] + C6 * h[6];
    float e1 = h[0] + C6 * h[2] - C4 * h[4] - C2 * h[6];
    float e2 = h[0] - C6 * h[2] - C4 * h[4] + C2 * h[6];
    float e3 = h[0] - C2 * h[2] + C4 * h[4] - C6 * h[6];
    float o0 = C1 * h[1] + C3 * h[3] + C5 * h[5] + C7 * h[7];
    float o1 = C3 * h[1] - C7 * h[3] - C1 * h[5] - C5 * h[7];
    float o2 = C5 * h[1] - C1 * h[3] + C7 * h[5] + C3 * h[7];
    float o3 = C7 * h[1] - C5 * h[3] + C3 * h[5] - C1 * h[7];
    p[0] = e0 + o0;  p[7] = e0 - o0;
    p[1] = e1 + o1;  p[6] = e1 - o1;
    p[2] = e2 + o2;  p[5] = e2 - o2;
    p[3] = e3 + o3;  p[4] = e3 - o3;
}

__global__ void __launch_bounds__(128, 12)
jpeg_tile_kernel(const float* __restrict__ img, float* __restrict__ out) {
    __shared__ float sY[16 * 72];   // 16 Y blocks
    __shared__ float sC[8 * 72];    // 4 Cb + 4 Cr blocks, in-place
    __shared__ float sAqTY[64], sBqTY[64];  // Y quant, transposed [v][u]
    __shared__ float sAqTC[64], sBqTC[64];  // chroma quant, transposed [v][u]

    const int t = threadIdx.x;

    if (t < 64) {
        int u = t >> 3, v = t & 7;
        float au = (u == 0) ? 0.70710678118654752f : 1.f;
        float av = (v == 0) ? 0.70710678118654752f : 1.f;
        float S = au * av * 0.25f;
        float qy = c_YTAB[t] * 0.4f;   // QUALITY=80 -> FACTOR=0.4
        float qc = c_CTAB[t] * 0.4f;
        sAqTY[v * 8 + u] = __fdividef(S, qy);  sBqTY[v * 8 + u] = S * qy;
        sAqTC[v * 8 + u] = __fdividef(S, qc);  sBqTC[v * 8 + u] = S * qc;
    }

    const int bid  = blockIdx.x;
    const int tx   = bid & 7;            // 8 tiles across (64 px)
    const int ty   = (bid >> 3) & 31;    // 32 tiles down (16 px)
    const int bimg = bid >> 8;

    const int sx  = t & 7;               // strip x (8 strips of 8 px)
    const int row = t >> 3;              // tile row 0..15
    const int px0 = tx * 64 + sx * 8;
    const int py0 = ty * 16 + row;

    const size_t plane = (size_t)IMG * IMG;
    const float* base = img + (size_t)bimg * 3 * plane + (size_t)py0 * IMG + px0;

    const int yb    = ((row >> 3) << 3) + sx;   // Y block (8 across, 2 down)
    const int ysw   = yb & 4;
    const int ybase = yb * 72 + (row & 7) * 9;

    // ---- E1: load row, RGB->Y (-128 folded), chroma partials (+shfl pair),
    //      row-DCT in regs, store Y v-coefs; even rows store chroma pixels.
    float y[8], cbp[4], crp[4];
    {
        float4 R0 = *(const float4*)(base);
        float4 G0 = *(const float4*)(base + plane);
        float4 B0 = *(const float4*)(base + 2 * plane);
        float Ra[4] = {R0.x, R0.y, R0.z, R0.w};
        float Ga[4] = {G0.x, G0.y, G0.z, G0.w};
        float Ba[4] = {B0.x, B0.y, B0.z, B0.w};
        #pragma unroll
        for (int c = 0; c < 4; c++) {
            float rr = Ra[c] * 255.f, gg = Ga[c] * 255.f, bb = Ba[c] * 255.f;
            y[c] = 0.299f * rr + 0.587f * gg + 0.114f * bb - 128.f;
            float cbv = -0.168736f * rr - 0.331264f * gg + 0.5f      * bb;
            float crv =  0.5f      * rr - 0.418688f * gg - 0.081312f * bb;
            if ((c & 1) == 0) { cbp[c >> 1] = cbv;  crp[c >> 1] = crv; }
            else              { cbp[c >> 1] += cbv; crp[c >> 1] += crv; }
        }
        float4 R1 = *(const float4*)(base + 4);
        float4 G1 = *(const float4*)(base + plane + 4);
        float4 B1 = *(const float4*)(base + 2 * plane + 4);
        float Rb[4] = {R1.x, R1.y, R1.z, R1.w};
        float Gb[4] = {G1.x, G1.y, G1.z, G1.w};
        float Bb[4] = {B1.x, B1.y, B1.z, B1.w};
        #pragma unroll
        for (int c = 0; c < 4; c++) {
            float rr = Rb[c] * 255.f, gg = Gb[c] * 255.f, bb = Bb[c] * 255.f;
            y[4 + c] = 0.299f * rr + 0.587f * gg + 0.114f * bb - 128.f;
            float cbv = -0.168736f * rr - 0.331264f * gg + 0.5f      * bb;
            float crv =  0.5f      * rr - 0.418688f * gg - 0.081312f * bb;
            if ((c & 1) == 0) { cbp[2 + (c >> 1)] = cbv;  crp[2 + (c >> 1)] = crv; }
            else              { cbp[2 + (c >> 1)] += cbv; crp[2 + (c >> 1)] += crv; }
        }
    }
    // combine vertical pair (rows r, r^1 are lanes t, t^8 — same warp)
    #pragma unroll
    for (int k = 0; k < 4; k++) {
        cbp[k] += __shfl_xor_sync(0xFFFFFFFFu, cbp[k], 8);
        crp[k] += __shfl_xor_sync(0xFFFFFFFFu, crp[k], 8);
    }
    if ((row & 1) == 0) {
        int cbB = sx >> 1, c0 = (sx & 1) * 4, cr_ = row >> 1;
        #pragma unroll
        for (int k = 0; k < 4; k++) {
            sC[cbB * 72       + cr_ * 9 + c0 + k] = cbp[k] * 0.25f;
            sC[(cbB + 4) * 72 + cr_ * 9 + c0 + k] = crp[k] * 0.25f;
        }
    }
    {
        float a[8];
        dct8_fwd(y, a);
        #pragma unroll
        for (int v = 0; v < 8; v++) sY[ybase + (v ^ ysw)] = a[v];
    }
    __syncthreads();

    // ---- E2: Y column pass in place (128 tasks); chroma row-DCT (t>=64).
    {
        int b = t >> 3, v = t & 7;
        int cbase = b * 72 + (v ^ (b & 4));
        float col[8];
        #pragma unroll
        for (int x = 0; x < 8; x++) col[x] = sY[cbase + x * 9];
        float cf[8];
        dct8_fwd(col, cf);

        const float4 qa0 = *(const float4*)&sAqTY[v * 8];
        const float4 qa1 = *(const float4*)&sAqTY[v * 8 + 4];
        const float4 qb0 = *(const float4*)&sBqTY[v * 8];
        const float4 qb1 = *(const float4*)&sBqTY[v * 8 + 4];
        const float Aq[8] = {qa0.x, qa0.y, qa0.z, qa0.w, qa1.x, qa1.y, qa1.z, qa1.w};
        const float Bq[8] = {qb0.x, qb0.y, qb0.z, qb0.w, qb1.x, qb1.y, qb1.z, qb1.w};
        float h[8];
        #pragma unroll
        for (int u = 0; u < 8; u++) {
            float c = cf[u] * Aq[u];
            float r = rintf(c);            // round-half-even == jnp.round
            float d = c - r;
            h[u] = (r + d * d * d) * Bq[u];
        }
        float hw[8];
        dct8_inv(h, hw);
        #pragma unroll
        for (int x = 0; x < 8; x++) sY[cbase + x * 9] = hw[x];
    }
    if (t >= 64) {    // chroma row-DCT, in place per-row
        int idx = t - 64;
        int b = idx >> 3, r = idx & 7;
        int rb = b * 72 + r * 9, sw = b & 4;
        float in[8];
        #pragma unroll
        for (int j = 0; j < 8; j++) in[j] = sC[rb + j];
        float a[8];
        dct8_fwd(in, a);
        #pragma unroll
        for (int v = 0; v < 8; v++) sC[rb + (v ^ sw)] = a[v];
    }
    __syncthreads();

    // ---- E3: chroma column pass in place (64 tasks).
    if (t < 64) {
        int b = t >> 3, v = t & 7;
        int cbase = b * 72 + (v ^ (b & 4));
        float col[8];
        #pragma unroll
        for (int x = 0; x < 8; x++) col[x] = sC[cbase + x * 9];
        float cf[8];
        dct8_fwd(col, cf);

        const float4 qa0 = *(const float4*)&sAqTC[v * 8];
        const float4 qa1 = *(const float4*)&sAqTC[v * 8 + 4];
        const float4 qb0 = *(const float4*)&sBqTC[v * 8];
        const float4 qb1 = *(const float4*)&sBqTC[v * 8 + 4];
        const float Aq[8] = {qa0.x, qa0.y, qa0.z, qa0.w, qa1.x, qa1.y, qa1.z, qa1.w};
        const float Bq[8] = {qb0.x, qb0.y, qb0.z, qb0.w, qb1.x, qb1.y, qb1.z, qb1.w};
        float h[8];
        #pragma unroll
        for (int u = 0; u < 8; u++) {
            float c = cf[u] * Aq[u];
            float r = rintf(c);
            float d = c - r;
            h[u] = (r + d * d * d) * Bq[u];
        }
        float hw[8];
        dct8_inv(h, hw);
        #pragma unroll
        for (int x = 0; x < 8; x++) sC[cbase + x * 9] = hw[x];
    }
    __syncthreads();

    // ---- E4: chroma row-inverse, in place per-row (64 tasks).
    if (t < 64) {
        int b = t >> 3, r = t & 7;
        int rb = b * 72 + r * 9, sw = b & 4;
        float hv[8];
        #pragma unroll
        for (int v = 0; v < 8; v++) hv[v] = sC[rb + (v ^ sw)];
        float p[8];
        dct8_inv(hv, p);
        #pragma unroll
        for (int j = 0; j < 8; j++) sC[rb + j] = p[j];
    }
    __syncthreads();

    // ---- E5: Y inverse row-DCT in regs, chroma read, YCbCr->RGB, store.
    float yp[8];
    {
        float hv[8];
        #pragma unroll
        for (int v = 0; v < 8; v++) hv[v] = sY[ybase + (v ^ ysw)];
        dct8_inv(hv, yp);
    }
    float cbq[4], crq[4];
    {
        int cbB = sx >> 1, c0 = (sx & 1) * 4, cr_ = row >> 1;
        #pragma unroll
        for (int k = 0; k < 4; k++) {
            cbq[k] = sC[cbB * 72       + cr_ * 9 + c0 + k];
            crq[k] = sC[(cbB + 4) * 72 + cr_ * 9 + c0 + k];
        }
    }
    float Rv[8], Gv[8], Bv[8];
    #pragma unroll
    for (int c = 0; c < 8; c++) {
        float yy = yp[c] + 128.f;
        float cb = cbq[c >> 1];
        float cr = crq[c >> 1];
        float rr = yy + 1.402f * cr;
        float gg = yy - 0.344136f * cb - 0.714136f * cr;
        float bb = yy + 1.772f * cb;
        Rv[c] = fminf(fmaxf(rr, 0.f), 255.f) * (1.f / 255.f);
        Gv[c] = fminf(fmaxf(gg, 0.f), 255.f) * (1.f / 255.f);
        Bv[c] = fminf(fmaxf(bb, 0.f), 255.f) * (1.f / 255.f);
    }
    float* op = out + (size_t)bimg * 3 * plane + (size_t)py0 * IMG + px0;
    *(float4*)(op)                 = make_float4(Rv[0], Rv[1], Rv[2], Rv[3]);
    *(float4*)(op + 4)             = make_float4(Rv[4], Rv[5], Rv[6], Rv[7]);
    *(float4*)(op + plane)         = make_float4(Gv[0], Gv[1], Gv[2], Gv[3]);
    *(float4*)(op + plane + 4)     = make_float4(Gv[4], Gv[5], Gv[6], Gv[7]);
    *(float4*)(op + 2 * plane)     = make_float4(Bv[0], Bv[1], Bv[2], Bv[3]);
    *(float4*)(op + 2 * plane + 4) = make_float4(Bv[4], Bv[5], Bv[6], Bv[7]);
}

extern "C" void kernel_launch(void* const* d_in, const int* in_sizes, int n_in,
                              void* d_out, int out_size) {
    const float* img = (const float*)d_in[0];
    float* out = (float*)d_out;
    int batch = in_sizes[0] / (3 * IMG * IMG);        // 32
    int tiles = batch * (IMG / 16) * (IMG / 64);      // 32 * 32 * 8 = 8192
    jpeg_tile_kernel<<<tiles, 128>>>(img, out);
}